// round 14
// baseline (speedup 1.0000x reference)
#include <cuda_runtime.h>

typedef unsigned long long ull;

#define Bb     1024
#define ITEMS  55
#define NSTR   (Bb*ITEMS)    /* 56320 */
#define EOS_TOK 129

#define OFF_CLSEMB 24576          /* 1024*24 */
#define OFF_STREMB 925696         /* 24576 + 1024*55*16 */

/* ---- scratch (device globals) ---- */
__device__ ull   g_tr[2*128*8];       /* 0.5*(gi_r + bih_r + bhh_r), packed unit pairs */
__device__ ull   g_tz[2*128*8];       /* 0.5*(gi_z + bih_z + bhh_z) */
__device__ ull   g_tn[2*128*8];       /* gi_n + bih_n (unscaled) */
__device__ float g_ctab[19*16];
__device__ float g_hbuf[2*NSTR*16];
__device__ float g_hcls[Bb*16];
__device__ unsigned char g_len[NSTR];

__constant__ int c_map[19] = {128,93,41,91,61,34,40,37,33,63,43,47,36,42,96,48,95,46,128};

__device__ __forceinline__ float htanh(float x) {
    float r; asm("tanh.approx.f32 %0, %1;" : "=f"(r) : "f"(x)); return r;
}
/* sigmoid with pre-halved argument: sig2(y) = 0.5*tanh(y)+0.5 where y = x/2 */
__device__ __forceinline__ float sig2(float y) {
    return fmaf(htanh(y), 0.5f, 0.5f);
}
__device__ __forceinline__ ull pack2(float x, float y) {
    ull r; asm("mov.b64 %0, {%1, %2};" : "=l"(r) : "f"(x), "f"(y)); return r;
}
__device__ __forceinline__ ull dup2(float x) {
    ull r; asm("mov.b64 %0, {%1, %1};" : "=l"(r) : "f"(x)); return r;
}
__device__ __forceinline__ void unpack2(ull v, float& x, float& y) {
    asm("mov.b64 {%0, %1}, %2;" : "=f"(x), "=f"(y) : "l"(v));
}
__device__ __forceinline__ ull ffma2(ull a, ull b, ull c) {
    ull d; asm("fma.rn.f32x2 %0, %1, %2, %3;" : "=l"(d) : "l"(a), "l"(b), "l"(c)); return d;
}
__device__ __forceinline__ ull fadd2(ull a, ull b) {
    ull d; asm("add.rn.f32x2 %0, %1, %2;" : "=l"(d) : "l"(a), "l"(b)); return d;
}

/* ================= K0: precompute gi tables (r,z pre-halved) ============== */
__global__ void k_tables(const float* __restrict__ emb,
                         const float* __restrict__ Wf, const float* __restrict__ bif, const float* __restrict__ bhf,
                         const float* __restrict__ Wb, const float* __restrict__ bib, const float* __restrict__ bhb,
                         const float* __restrict__ rW, const float* __restrict__ rb)
{
    int idx = blockIdx.x * blockDim.x + threadIdx.x;
    if (idx < 4096) {
        int dir = idx >> 11;
        int c   = (idx >> 4) & 127;
        int jj  = idx & 15;
        const float* W  = dir ? Wb : Wf;
        const float* bi = dir ? bib : bif;
        const float* bh = dir ? bhb : bhf;
        float e[16];
        #pragma unroll
        for (int d = 0; d < 16; d++) e[d] = (c == 0) ? 0.f : emb[c*16 + d];
        float v[3];
        #pragma unroll
        for (int g = 0; g < 3; g++) {
            float a = bi[g*16 + jj];
            #pragma unroll
            for (int d = 0; d < 16; d++) a += e[d] * W[(g*16 + jj)*16 + d];
            v[g] = a;
        }
        v[0] = 0.5f * (v[0] + bh[jj]);
        v[1] = 0.5f * (v[1] + bh[16 + jj]);
        int o = ((dir*128 + c)*8 + (jj >> 1))*2 + (jj & 1);
        ((float*)g_tr)[o] = v[0];
        ((float*)g_tz)[o] = v[1];
        ((float*)g_tn)[o] = v[2];
    } else if (idx < 4096 + 304) {
        int t = idx - 4096;
        int cls = t >> 4, jj = t & 15;
        int c = c_map[cls];
        float v = rb[jj];
        #pragma unroll
        for (int d = 0; d < 16; d++) v += emb[c*16 + d] * rW[jj*16 + d];
        g_ctab[t] = v;
    }
}

/* ================= K1: inv_class_emb output (side stream) ================= */
__global__ void __launch_bounds__(256) k_clsemb(const int* __restrict__ ocl,
                                                const float* __restrict__ emb,
                                                float* __restrict__ out)
{
    int q = blockIdx.x * blockDim.x + threadIdx.x;
    if (q >= NSTR*4) return;
    int item = q >> 2, d4 = q & 3;
    int c = c_map[ocl[item]];
    const float4* e4 = (const float4*)emb;
    ((float4*)out)[q] = e4[c*4 + d4];
}

/* ================= K2: str_emb output + lengths (side stream) ============= */
__global__ void __launch_bounds__(256) k_stremb(const int* __restrict__ strs,
                                                const float* __restrict__ emb,
                                                float* __restrict__ out)
{
    __shared__ float4 semb[130*4];
    __shared__ unsigned char sch[8][80];
    int tid = threadIdx.x;
    const float4* e4 = (const float4*)emb;
    for (int i = tid; i < 520; i += 256) {
        float4 v = e4[i];
        if (i < 4) v = make_float4(0.f, 0.f, 0.f, 0.f);
        semb[i] = v;
    }
    int w = tid >> 5, lane = tid & 31;
    int n = blockIdx.x * 8 + w;
    const int* sp = strs + (size_t)n * 80;
    int c0 = sp[lane];
    int c1 = sp[32 + lane];
    int c2 = (lane < 16) ? sp[64 + lane] : 0;
    unsigned m0 = __ballot_sync(0xffffffffu, c0 != 0);
    unsigned m1 = __ballot_sync(0xffffffffu, c1 != 0);
    unsigned m2 = __ballot_sync(0xffffffffu, (lane < 16) && (c2 != 0));
    int len = __popc(m0) + __popc(m1) + __popc(m2);
    sch[w][lane]      = (unsigned char)c0;
    sch[w][32 + lane] = (unsigned char)c1;
    if (lane < 16) sch[w][64 + lane] = (unsigned char)c2;
    if (lane == 0) g_len[n] = (unsigned char)len;
    __syncthreads();
    float4* o4 = (float4*)out + (size_t)n * 320;
    #pragma unroll
    for (int it = 0; it < 10; it++) {
        int flat = it*32 + lane;
        int t = flat >> 2, d4 = flat & 3;
        int c = (t == len) ? EOS_TOK : (int)sch[w][t];
        o4[flat] = semb[c*4 + d4];
    }
}

/* ====== K3: bidirectional GRU — identical to R13 except occupancy 4 ====== */
__global__ void __launch_bounds__(128, 4) k_gru(const int* __restrict__ strs,
                                                const float* __restrict__ Whf, const float* __restrict__ bhf,
                                                const float* __restrict__ Whb, const float* __restrict__ bhb)
{
    __shared__ ull s_tr[1024], s_tz[1024], s_tn[1024];
    __shared__ unsigned char sch[16*80];
    int tid = threadIdx.x;
    int dir = blockIdx.y;
    int base = blockIdx.x * 16;

    {
        const float4* s0 = (const float4*)(g_tr + dir*1024);
        const float4* s1 = (const float4*)(g_tz + dir*1024);
        const float4* s2 = (const float4*)(g_tn + dir*1024);
        for (int i = tid; i < 512; i += 128) {
            ((float4*)s_tr)[i] = s0[i];
            ((float4*)s_tz)[i] = s1[i];
            ((float4*)s_tn)[i] = s2[i];
        }
    }
    const int* sp = strs + (size_t)base * 80;
    for (int i = tid; i < 1280; i += 128) sch[i] = (unsigned char)sp[i];
    __syncthreads();

    int j = tid & 7;
    int s = tid >> 3;
    unsigned gm = 0xFFu << (tid & 24);

    int len;
    {
        const unsigned char* ch = &sch[s*80];
        int cnt = 0;
        #pragma unroll
        for (int i = 0; i < 10; i++) cnt += (ch[j*10 + i] != 0);
        #pragma unroll
        for (int o = 4; o; o >>= 1) cnt += __shfl_xor_sync(gm, cnt, o, 8);
        len = cnt;
    }

    const float* Wp = dir ? Whb : Whf;
    const float* bh = dir ? bhb : bhf;
    int j2 = j * 2;
    ull wr[16], wz[16], wn[16];
    #pragma unroll
    for (int k = 0; k < 16; k++) {
        wr[k] = pack2(0.5f*Wp[j2*16 + k],      0.5f*Wp[(j2+1)*16 + k]);
        wz[k] = pack2(0.5f*Wp[(16+j2)*16 + k], 0.5f*Wp[(17+j2)*16 + k]);
        wn[k] = pack2(Wp[(32+j2)*16 + k],      Wp[(33+j2)*16 + k]);
    }
    ull bhn2 = pack2(bh[32 + j2], bh[33 + j2]);

    const unsigned char* ch = &sch[s*80];
    float h0 = 0.f, h1 = 0.f;
    int pos = dir ? (len - 1) : 0;
    int dstep = dir ? -1 : 1;
    for (int t = 0; t < len; t++, pos += dstep) {
        int c = ch[pos];
        ull ar  = s_tr[c*8 + j];
        ull az  = s_tz[c*8 + j];
        ull gn  = s_tn[c*8 + j];
        ull ar1 = 0, az1 = 0, an0 = bhn2, an1 = 0;
        #pragma unroll
        for (int kk = 0; kk < 8; kk++) {
            float hx = __shfl_sync(gm, h0, kk, 8);
            float hy = __shfl_sync(gm, h1, kk, 8);
            ull d0 = dup2(hx), d1 = dup2(hy);
            ar  = ffma2(wr[2*kk],   d0, ar);
            ar1 = ffma2(wr[2*kk+1], d1, ar1);
            az  = ffma2(wz[2*kk],   d0, az);
            az1 = ffma2(wz[2*kk+1], d1, az1);
            an0 = ffma2(wn[2*kk],   d0, an0);
            an1 = ffma2(wn[2*kk+1], d1, an1);
        }
        ar = fadd2(ar, ar1); az = fadd2(az, az1); an0 = fadd2(an0, an1);
        float srx, sry, szx, szy, ahx, ahy, gnx, gny;
        unpack2(ar, srx, sry); unpack2(az, szx, szy);
        unpack2(an0, ahx, ahy); unpack2(gn, gnx, gny);
        float r0 = sig2(srx), r1 = sig2(sry);
        float z0 = sig2(szx), z1 = sig2(szy);
        float n0 = htanh(fmaf(r0, ahx, gnx));
        float n1 = htanh(fmaf(r1, ahy, gny));
        h0 = n0 + z0*(h0 - n0);
        h1 = n1 + z1*(h1 - n1);
    }
    ((float2*)g_hbuf)[((size_t)dir*NSTR + base + s)*8 + j] = make_float2(h0, h1);
}

/* ================= K4: class-branch vanilla RNN (side stream) ============= */
__global__ void __launch_bounds__(128) k_cls(const int* __restrict__ ocl,
                                             const float* __restrict__ Whh,
                                             const float* __restrict__ bhh)
{
    __shared__ float sct[19*16];
    __shared__ unsigned char soc[8*55];
    int tid = threadIdx.x;
    int base = blockIdx.x * 8;
    for (int i = tid; i < 304; i += 128) sct[i] = g_ctab[i];
    for (int i = tid; i < 440; i += 128) soc[i] = (unsigned char)ocl[base*55 + i];

    int j = tid & 15;
    float w[16];
    const float4* W4 = (const float4*)Whh;
    #pragma unroll
    for (int kk = 0; kk < 4; kk++) {
        float4 a = W4[j*4 + kk];
        w[kk*4+0]=a.x; w[kk*4+1]=a.y; w[kk*4+2]=a.z; w[kk*4+3]=a.w;
    }
    float bhv = bhh[j];
    __syncthreads();

    int s = tid >> 4;
    unsigned gmask = 0xFFFFu << (tid & 16);
    const unsigned char* oc = &soc[s * 55];
    int cnt = 0;
    #pragma unroll
    for (int i = 0; i < 4; i++) { int p = j + 16*i; cnt += (p < 55) ? (oc[p] != 18) : 0; }
    #pragma unroll
    for (int o = 8; o; o >>= 1) cnt += __shfl_xor_sync(gmask, cnt, o, 16);
    int len = cnt;

    float h = 0.f;
    for (int t = 0; t < len; t++) {
        int c = oc[t];
        float acc = sct[c*16 + j] + bhv;
        #pragma unroll
        for (int k = 0; k < 16; k++) {
            float hk = __shfl_sync(gmask, h, k, 16);
            acc += w[k]*hk;
        }
        h = htanh(acc);
    }
    g_hcls[(base + s)*16 + j] = h;
}

/* ================= K5: pooling + fusion MLP (1 item per block) ============ */
__global__ void __launch_bounds__(128) k_fuse(const float* __restrict__ W1, const float* __restrict__ b1,
                                              const float* __restrict__ W2, const float* __restrict__ b2,
                                              float* __restrict__ out)
{
    __shared__ float part[4][32];
    __shared__ float smask[56];
    __shared__ float comb[48];
    __shared__ float h1s[16];
    int t = threadIdx.x;
    int b = blockIdx.x;
    int nb = b * ITEMS;
    int grp = t >> 5, col = t & 31;

    if (t < ITEMS) smask[t] = g_len[nb + t] ? 1.f : 0.f;
    if (t == ITEMS) smask[t] = 0.f;
    __syncthreads();

    const float* hf = &g_hbuf[0];
    const float* hb = &g_hbuf[(size_t)NSTR * 16];
    float acc = 0.f;
    for (int i = grp; i < ITEMS; i += 4) {
        float hv = (col < 16) ? hf[(nb + i)*16 + col] : hb[(nb + i)*16 + (col - 16)];
        acc += smask[i] * hv;
    }
    part[grp][col] = acc;
    __syncthreads();

    if (t < 32) {
        float p = part[0][t] + part[1][t] + part[2][t] + part[3][t];
        float cnt = 0.f;
        #pragma unroll
        for (int i = 0; i < ITEMS; i++) cnt += smask[i];
        comb[16 + t] = p / (cnt + 1e-8f);
        if (t < 16) comb[t] = g_hcls[b*16 + t];
    }
    __syncthreads();
    if (t < 16) {
        float a = b1[t];
        #pragma unroll
        for (int k = 0; k < 48; k++) a += W1[t*48 + k] * comb[k];
        h1s[t] = fmaxf(a, 0.f);
    }
    __syncthreads();
    if (t < 24) {
        float o = b2[t];
        #pragma unroll
        for (int k = 0; k < 16; k++) o += W2[t*16 + k] * h1s[k];
        out[b*24 + t] = o;
    }
}

/* ---- side stream + fork/join events, created once at static init ---- */
struct SideCtx {
    cudaStream_t s;
    cudaEvent_t e_fork, e_join;
    SideCtx() {
        cudaStreamCreateWithFlags(&s, cudaStreamNonBlocking);
        cudaEventCreateWithFlags(&e_fork, cudaEventDisableTiming);
        cudaEventCreateWithFlags(&e_join, cudaEventDisableTiming);
    }
};
static SideCtx g_side;

extern "C" void kernel_launch(void* const* d_in, const int* in_sizes, int n_in,
                              void* d_out, int out_size)
{
    const int*   ocl  = (const int*)d_in[0];
    const int*   strs = (const int*)d_in[1];
    const float* emb  = (const float*)d_in[2];
    const float* rW   = (const float*)d_in[3];
    const float* rWhh = (const float*)d_in[4];
    const float* rbih = (const float*)d_in[5];
    const float* rbhh = (const float*)d_in[6];
    const float* gWf  = (const float*)d_in[7];
    const float* gWhf = (const float*)d_in[8];
    const float* gbif = (const float*)d_in[9];
    const float* gbhf = (const float*)d_in[10];
    const float* gWb  = (const float*)d_in[11];
    const float* gWhb = (const float*)d_in[12];
    const float* gbib = (const float*)d_in[13];
    const float* gbhb = (const float*)d_in[14];
    const float* W1   = (const float*)d_in[15];
    const float* b1   = (const float*)d_in[16];
    const float* W2   = (const float*)d_in[17];
    const float* b2   = (const float*)d_in[18];
    float* out = (float*)d_out;

    /* main stream: tables -> GRU -> (join) fuse */
    k_tables<<<18, 256>>>(emb, gWf, gbif, gbhf, gWb, gbib, gbhb, rW, rbih);

    /* fork: side stream runs stremb + clsemb + cls concurrently with GRU */
    cudaEventRecord(g_side.e_fork, 0);
    cudaStreamWaitEvent(g_side.s, g_side.e_fork, 0);
    k_stremb<<<7040, 256, 0, g_side.s>>>(strs, emb, out + OFF_STREMB);
    k_clsemb<<<880, 256, 0, g_side.s>>>(ocl, emb, out + OFF_CLSEMB);
    k_cls<<<128, 128, 0, g_side.s>>>(ocl, rWhh, rbhh);
    cudaEventRecord(g_side.e_join, g_side.s);

    dim3 gg(3520, 2);
    k_gru<<<gg, 128>>>(strs, gWhf, gbhf, gWhb, gbhb);

    /* join before fuse */
    cudaStreamWaitEvent(0, g_side.e_join, 0);
    k_fuse<<<1024, 128>>>(W1, b1, W2, b2, out);
}

// round 15
// speedup vs baseline: 1.0626x; 1.0626x over previous
#include <cuda_runtime.h>

typedef unsigned long long ull;

#define Bb     1024
#define ITEMS  55
#define NSTR   (Bb*ITEMS)    /* 56320 */
#define EOS_TOK 129

#define OFF_CLSEMB 24576          /* 1024*24 */
#define OFF_STREMB 925696         /* 24576 + 1024*55*16 */

/* ---- scratch (device globals) ---- */
__device__ ull   g_tr[2*128*8];       /* 0.5*(gi_r + bih_r + bhh_r), packed unit pairs */
__device__ ull   g_tz[2*128*8];       /* 0.5*(gi_z + bih_z + bhh_z) */
__device__ ull   g_tn[2*128*8];       /* gi_n + bih_n (unscaled) */
__device__ float g_ctab[19*16];
__device__ float g_hbuf[2*NSTR*16];
__device__ float g_hcls[Bb*16];
__device__ unsigned char g_len[NSTR];

__constant__ int c_map[19] = {128,93,41,91,61,34,40,37,33,63,43,47,36,42,96,48,95,46,128};

__device__ __forceinline__ float htanh(float x) {
    float r; asm("tanh.approx.f32 %0, %1;" : "=f"(r) : "f"(x)); return r;
}
__device__ __forceinline__ float sig2(float y) {   /* arg pre-halved */
    return fmaf(htanh(y), 0.5f, 0.5f);
}
__device__ __forceinline__ ull pack2(float x, float y) {
    ull r; asm("mov.b64 %0, {%1, %2};" : "=l"(r) : "f"(x), "f"(y)); return r;
}
__device__ __forceinline__ ull dup2(float x) {
    ull r; asm("mov.b64 %0, {%1, %1};" : "=l"(r) : "f"(x)); return r;
}
__device__ __forceinline__ void unpack2(ull v, float& x, float& y) {
    asm("mov.b64 {%0, %1}, %2;" : "=f"(x), "=f"(y) : "l"(v));
}
__device__ __forceinline__ ull ffma2(ull a, ull b, ull c) {
    ull d; asm("fma.rn.f32x2 %0, %1, %2, %3;" : "=l"(d) : "l"(a), "l"(b), "l"(c)); return d;
}
__device__ __forceinline__ ull fadd2(ull a, ull b) {
    ull d; asm("add.rn.f32x2 %0, %1, %2;" : "=l"(d) : "l"(a), "l"(b)); return d;
}

/* ================= K0: precompute gi tables (r,z pre-halved) ============== */
__global__ void k_tables(const float* __restrict__ emb,
                         const float* __restrict__ Wf, const float* __restrict__ bif, const float* __restrict__ bhf,
                         const float* __restrict__ Wb, const float* __restrict__ bib, const float* __restrict__ bhb,
                         const float* __restrict__ rW, const float* __restrict__ rb)
{
    int idx = blockIdx.x * blockDim.x + threadIdx.x;
    if (idx < 4096) {
        int dir = idx >> 11;
        int c   = (idx >> 4) & 127;
        int jj  = idx & 15;
        const float* W  = dir ? Wb : Wf;
        const float* bi = dir ? bib : bif;
        const float* bh = dir ? bhb : bhf;
        float e[16];
        #pragma unroll
        for (int d = 0; d < 16; d++) e[d] = (c == 0) ? 0.f : emb[c*16 + d];
        float v[3];
        #pragma unroll
        for (int g = 0; g < 3; g++) {
            float a = bi[g*16 + jj];
            #pragma unroll
            for (int d = 0; d < 16; d++) a += e[d] * W[(g*16 + jj)*16 + d];
            v[g] = a;
        }
        v[0] = 0.5f * (v[0] + bh[jj]);
        v[1] = 0.5f * (v[1] + bh[16 + jj]);
        int o = ((dir*128 + c)*8 + (jj >> 1))*2 + (jj & 1);
        ((float*)g_tr)[o] = v[0];
        ((float*)g_tz)[o] = v[1];
        ((float*)g_tn)[o] = v[2];
    } else if (idx < 4096 + 304) {
        int t = idx - 4096;
        int cls = t >> 4, jj = t & 15;
        int c = c_map[cls];
        float v = rb[jj];
        #pragma unroll
        for (int d = 0; d < 16; d++) v += emb[c*16 + d] * rW[jj*16 + d];
        g_ctab[t] = v;
    }
}

/* ================= K1: inv_class_emb output (side stream) ================= */
__global__ void __launch_bounds__(256) k_clsemb(const int* __restrict__ ocl,
                                                const float* __restrict__ emb,
                                                float* __restrict__ out)
{
    int q = blockIdx.x * blockDim.x + threadIdx.x;
    if (q >= NSTR*4) return;
    int item = q >> 2, d4 = q & 3;
    int c = c_map[ocl[item]];
    const float4* e4 = (const float4*)emb;
    ((float4*)out)[q] = e4[c*4 + d4];
}

/* ================= K2: str_emb output + lengths (side stream) ============= */
__global__ void __launch_bounds__(256) k_stremb(const int* __restrict__ strs,
                                                const float* __restrict__ emb,
                                                float* __restrict__ out)
{
    __shared__ float4 semb[130*4];
    __shared__ unsigned char sch[8][80];
    int tid = threadIdx.x;
    const float4* e4 = (const float4*)emb;
    for (int i = tid; i < 520; i += 256) {
        float4 v = e4[i];
        if (i < 4) v = make_float4(0.f, 0.f, 0.f, 0.f);
        semb[i] = v;
    }
    int w = tid >> 5, lane = tid & 31;
    int n = blockIdx.x * 8 + w;
    const int* sp = strs + (size_t)n * 80;
    int c0 = sp[lane];
    int c1 = sp[32 + lane];
    int c2 = (lane < 16) ? sp[64 + lane] : 0;
    unsigned m0 = __ballot_sync(0xffffffffu, c0 != 0);
    unsigned m1 = __ballot_sync(0xffffffffu, c1 != 0);
    unsigned m2 = __ballot_sync(0xffffffffu, (lane < 16) && (c2 != 0));
    int len = __popc(m0) + __popc(m1) + __popc(m2);
    sch[w][lane]      = (unsigned char)c0;
    sch[w][32 + lane] = (unsigned char)c1;
    if (lane < 16) sch[w][64 + lane] = (unsigned char)c2;
    if (lane == 0) g_len[n] = (unsigned char)len;
    __syncthreads();
    float4* o4 = (float4*)out + (size_t)n * 320;
    #pragma unroll
    for (int it = 0; it < 10; it++) {
        int flat = it*32 + lane;
        int t = flat >> 2, d4 = flat & 3;
        int c = (t == len) ? EOS_TOK : (int)sch[w][t];
        o4[flat] = semb[c*4 + d4];
    }
}

/* ====== K3: bidirectional GRU — R13 core (occ 3) + table prefetch ========= */
__global__ void __launch_bounds__(128, 3) k_gru(const int* __restrict__ strs,
                                                const float* __restrict__ Whf, const float* __restrict__ bhf,
                                                const float* __restrict__ Whb, const float* __restrict__ bhb)
{
    __shared__ ull s_tr[1024], s_tz[1024], s_tn[1024];
    __shared__ unsigned char sch[16*80];
    int tid = threadIdx.x;
    int dir = blockIdx.y;
    int base = blockIdx.x * 16;

    {
        const float4* s0 = (const float4*)(g_tr + dir*1024);
        const float4* s1 = (const float4*)(g_tz + dir*1024);
        const float4* s2 = (const float4*)(g_tn + dir*1024);
        for (int i = tid; i < 512; i += 128) {
            ((float4*)s_tr)[i] = s0[i];
            ((float4*)s_tz)[i] = s1[i];
            ((float4*)s_tn)[i] = s2[i];
        }
    }
    const int* sp = strs + (size_t)base * 80;
    for (int i = tid; i < 1280; i += 128) sch[i] = (unsigned char)sp[i];
    __syncthreads();

    int j = tid & 7;
    int s = tid >> 3;
    unsigned gm = 0xFFu << (tid & 24);

    int len;
    {
        const unsigned char* ch = &sch[s*80];
        int cnt = 0;
        #pragma unroll
        for (int i = 0; i < 10; i++) cnt += (ch[j*10 + i] != 0);
        #pragma unroll
        for (int o = 4; o; o >>= 1) cnt += __shfl_xor_sync(gm, cnt, o, 8);
        len = cnt;
    }

    const float* Wp = dir ? Whb : Whf;
    const float* bh = dir ? bhb : bhf;
    int j2 = j * 2;
    ull wr[16], wz[16], wn[16];
    #pragma unroll
    for (int k = 0; k < 16; k++) {
        wr[k] = pack2(0.5f*Wp[j2*16 + k],      0.5f*Wp[(j2+1)*16 + k]);
        wz[k] = pack2(0.5f*Wp[(16+j2)*16 + k], 0.5f*Wp[(17+j2)*16 + k]);
        wn[k] = pack2(Wp[(32+j2)*16 + k],      Wp[(33+j2)*16 + k]);
    }
    ull bhn2 = pack2(bh[32 + j2], bh[33 + j2]);

    const unsigned char* ch = &sch[s*80];
    float h0 = 0.f, h1 = 0.f;
    if (len > 0) {
        int dstep = dir ? -1 : 1;
        int pos = dir ? (len - 1) : 0;
        int c0i = ch[pos];
        ull gr = s_tr[c0i*8 + j], gz = s_tz[c0i*8 + j], gn = s_tn[c0i*8 + j];
        for (int t = 0; t < len; t++) {
            /* prefetch next step's table rows off the critical path */
            int pn = pos + dstep;
            int pcl = (t + 1 < len) ? pn : 0;
            int cn = ch[pcl];
            ull grn = s_tr[cn*8 + j], gzn = s_tz[cn*8 + j], gnn = s_tn[cn*8 + j];

            ull ar  = gr;             /* accumulator init = prefetched table row */
            ull az  = gz;
            ull ar1 = 0, az1 = 0, an0 = bhn2, an1 = 0;
            #pragma unroll
            for (int kk = 0; kk < 8; kk++) {
                float hx = __shfl_sync(gm, h0, kk, 8);
                float hy = __shfl_sync(gm, h1, kk, 8);
                ull d0 = dup2(hx), d1 = dup2(hy);
                ar  = ffma2(wr[2*kk],   d0, ar);
                ar1 = ffma2(wr[2*kk+1], d1, ar1);
                az  = ffma2(wz[2*kk],   d0, az);
                az1 = ffma2(wz[2*kk+1], d1, az1);
                an0 = ffma2(wn[2*kk],   d0, an0);
                an1 = ffma2(wn[2*kk+1], d1, an1);
            }
            ar = fadd2(ar, ar1); az = fadd2(az, az1); an0 = fadd2(an0, an1);
            float srx, sry, szx, szy, ahx, ahy, gnx, gny;
            unpack2(ar, srx, sry); unpack2(az, szx, szy);
            unpack2(an0, ahx, ahy); unpack2(gn, gnx, gny);
            float r0 = sig2(srx), r1 = sig2(sry);
            float z0 = sig2(szx), z1 = sig2(szy);
            float n0 = htanh(fmaf(r0, ahx, gnx));
            float n1 = htanh(fmaf(r1, ahy, gny));
            h0 = n0 + z0*(h0 - n0);
            h1 = n1 + z1*(h1 - n1);

            gr = grn; gz = gzn; gn = gnn; pos = pn;
        }
    }
    ((float2*)g_hbuf)[((size_t)dir*NSTR + base + s)*8 + j] = make_float2(h0, h1);
}

/* ================= K4: class-branch vanilla RNN (side stream) ============= */
__global__ void __launch_bounds__(128) k_cls(const int* __restrict__ ocl,
                                             const float* __restrict__ Whh,
                                             const float* __restrict__ bhh)
{
    __shared__ float sct[19*16];
    __shared__ unsigned char soc[8*55];
    int tid = threadIdx.x;
    int base = blockIdx.x * 8;
    for (int i = tid; i < 304; i += 128) sct[i] = g_ctab[i];
    for (int i = tid; i < 440; i += 128) soc[i] = (unsigned char)ocl[base*55 + i];

    int j = tid & 15;
    float w[16];
    const float4* W4 = (const float4*)Whh;
    #pragma unroll
    for (int kk = 0; kk < 4; kk++) {
        float4 a = W4[j*4 + kk];
        w[kk*4+0]=a.x; w[kk*4+1]=a.y; w[kk*4+2]=a.z; w[kk*4+3]=a.w;
    }
    float bhv = bhh[j];
    __syncthreads();

    int s = tid >> 4;
    unsigned gmask = 0xFFFFu << (tid & 16);
    const unsigned char* oc = &soc[s * 55];
    int cnt = 0;
    #pragma unroll
    for (int i = 0; i < 4; i++) { int p = j + 16*i; cnt += (p < 55) ? (oc[p] != 18) : 0; }
    #pragma unroll
    for (int o = 8; o; o >>= 1) cnt += __shfl_xor_sync(gmask, cnt, o, 16);
    int len = cnt;

    float h = 0.f;
    for (int t = 0; t < len; t++) {
        int c = oc[t];
        float acc = sct[c*16 + j] + bhv;
        #pragma unroll
        for (int k = 0; k < 16; k++) {
            float hk = __shfl_sync(gmask, h, k, 16);
            acc += w[k]*hk;
        }
        h = htanh(acc);
    }
    g_hcls[(base + s)*16 + j] = h;
}

/* ================= K5: pooling + fusion MLP (1 item per block) ============ */
__global__ void __launch_bounds__(128) k_fuse(const float* __restrict__ W1, const float* __restrict__ b1,
                                              const float* __restrict__ W2, const float* __restrict__ b2,
                                              float* __restrict__ out)
{
    __shared__ float part[4][32];
    __shared__ float smask[56];
    __shared__ float comb[48];
    __shared__ float h1s[16];
    int t = threadIdx.x;
    int b = blockIdx.x;
    int nb = b * ITEMS;
    int grp = t >> 5, col = t & 31;

    if (t < ITEMS) smask[t] = g_len[nb + t] ? 1.f : 0.f;
    if (t == ITEMS) smask[t] = 0.f;
    __syncthreads();

    const float* hf = &g_hbuf[0];
    const float* hb = &g_hbuf[(size_t)NSTR * 16];
    float acc = 0.f;
    for (int i = grp; i < ITEMS; i += 4) {
        float hv = (col < 16) ? hf[(nb + i)*16 + col] : hb[(nb + i)*16 + (col - 16)];
        acc += smask[i] * hv;
    }
    part[grp][col] = acc;
    __syncthreads();

    if (t < 32) {
        float p = part[0][t] + part[1][t] + part[2][t] + part[3][t];
        float cnt = 0.f;
        #pragma unroll
        for (int i = 0; i < ITEMS; i++) cnt += smask[i];
        comb[16 + t] = p / (cnt + 1e-8f);
        if (t < 16) comb[t] = g_hcls[b*16 + t];
    }
    __syncthreads();
    if (t < 16) {
        float a = b1[t];
        #pragma unroll
        for (int k = 0; k < 48; k++) a += W1[t*48 + k] * comb[k];
        h1s[t] = fmaxf(a, 0.f);
    }
    __syncthreads();
    if (t < 24) {
        float o = b2[t];
        #pragma unroll
        for (int k = 0; k < 16; k++) o += W2[t*16 + k] * h1s[k];
        out[b*24 + t] = o;
    }
}

/* ---- side stream + fork/join events, created once at static init ---- */
struct SideCtx {
    cudaStream_t s;
    cudaEvent_t e_fork, e_join;
    SideCtx() {
        cudaStreamCreateWithFlags(&s, cudaStreamNonBlocking);
        cudaEventCreateWithFlags(&e_fork, cudaEventDisableTiming);
        cudaEventCreateWithFlags(&e_join, cudaEventDisableTiming);
    }
};
static SideCtx g_side;

extern "C" void kernel_launch(void* const* d_in, const int* in_sizes, int n_in,
                              void* d_out, int out_size)
{
    const int*   ocl  = (const int*)d_in[0];
    const int*   strs = (const int*)d_in[1];
    const float* emb  = (const float*)d_in[2];
    const float* rW   = (const float*)d_in[3];
    const float* rWhh = (const float*)d_in[4];
    const float* rbih = (const float*)d_in[5];
    const float* rbhh = (const float*)d_in[6];
    const float* gWf  = (const float*)d_in[7];
    const float* gWhf = (const float*)d_in[8];
    const float* gbif = (const float*)d_in[9];
    const float* gbhf = (const float*)d_in[10];
    const float* gWb  = (const float*)d_in[11];
    const float* gWhb = (const float*)d_in[12];
    const float* gbib = (const float*)d_in[13];
    const float* gbhb = (const float*)d_in[14];
    const float* W1   = (const float*)d_in[15];
    const float* b1   = (const float*)d_in[16];
    const float* W2   = (const float*)d_in[17];
    const float* b2   = (const float*)d_in[18];
    float* out = (float*)d_out;

    /* main stream: tables -> GRU -> (join) fuse */
    k_tables<<<18, 256>>>(emb, gWf, gbif, gbhf, gWb, gbib, gbhb, rW, rbih);

    /* fork: side stream runs stremb + clsemb + cls concurrently with GRU */
    cudaEventRecord(g_side.e_fork, 0);
    cudaStreamWaitEvent(g_side.s, g_side.e_fork, 0);
    k_stremb<<<7040, 256, 0, g_side.s>>>(strs, emb, out + OFF_STREMB);
    k_clsemb<<<880, 256, 0, g_side.s>>>(ocl, emb, out + OFF_CLSEMB);
    k_cls<<<128, 128, 0, g_side.s>>>(ocl, rWhh, rbhh);
    cudaEventRecord(g_side.e_join, g_side.s);

    dim3 gg(3520, 2);
    k_gru<<<gg, 128>>>(strs, gWhf, gbhf, gWhb, gbhb);

    /* join before fuse */
    cudaStreamWaitEvent(0, g_side.e_join, 0);
    k_fuse<<<1024, 128>>>(W1, b1, W2, b2, out);
}

// round 16
// speedup vs baseline: 1.1186x; 1.0527x over previous
#include <cuda_runtime.h>

typedef unsigned long long ull;

#define Bb     1024
#define ITEMS  55
#define NSTR   (Bb*ITEMS)    /* 56320 */
#define EOS_TOK 129

#define OFF_CLSEMB 24576          /* 1024*24 */
#define OFF_STREMB 925696         /* 24576 + 1024*55*16 */

/* ---- scratch (device globals) ---- */
__device__ ull   g_tr[2*128*8];       /* 0.5*(gi_r + bih_r + bhh_r), packed unit pairs */
__device__ ull   g_tz[2*128*8];       /* 0.5*(gi_z + bih_z + bhh_z) */
__device__ ull   g_tn[2*128*8];       /* gi_n + bih_n (unscaled) */
__device__ float g_ctab[19*16];
__device__ float g_hbuf[2*NSTR*16];
__device__ float g_hcls[Bb*16];
__device__ unsigned char g_len[NSTR];

__constant__ int c_map[19] = {128,93,41,91,61,34,40,37,33,63,43,47,36,42,96,48,95,46,128};

__device__ __forceinline__ float htanh(float x) {
    float r; asm("tanh.approx.f32 %0, %1;" : "=f"(r) : "f"(x)); return r;
}
__device__ __forceinline__ float sig2(float y) {   /* arg pre-halved */
    return fmaf(htanh(y), 0.5f, 0.5f);
}
__device__ __forceinline__ ull pack2(float x, float y) {
    ull r; asm("mov.b64 %0, {%1, %2};" : "=l"(r) : "f"(x), "f"(y)); return r;
}
__device__ __forceinline__ ull dup2(float x) {
    ull r; asm("mov.b64 %0, {%1, %1};" : "=l"(r) : "f"(x)); return r;
}
__device__ __forceinline__ void unpack2(ull v, float& x, float& y) {
    asm("mov.b64 {%0, %1}, %2;" : "=f"(x), "=f"(y) : "l"(v));
}
__device__ __forceinline__ ull ffma2(ull a, ull b, ull c) {
    ull d; asm("fma.rn.f32x2 %0, %1, %2, %3;" : "=l"(d) : "l"(a), "l"(b), "l"(c)); return d;
}
__device__ __forceinline__ ull fadd2(ull a, ull b) {
    ull d; asm("add.rn.f32x2 %0, %1, %2;" : "=l"(d) : "l"(a), "l"(b)); return d;
}

/* ================= K0: precompute gi tables (r,z pre-halved) ============== */
__global__ void k_tables(const float* __restrict__ emb,
                         const float* __restrict__ Wf, const float* __restrict__ bif, const float* __restrict__ bhf,
                         const float* __restrict__ Wb, const float* __restrict__ bib, const float* __restrict__ bhb,
                         const float* __restrict__ rW, const float* __restrict__ rb)
{
    int idx = blockIdx.x * blockDim.x + threadIdx.x;
    if (idx < 4096) {
        int dir = idx >> 11;
        int c   = (idx >> 4) & 127;
        int jj  = idx & 15;
        const float* W  = dir ? Wb : Wf;
        const float* bi = dir ? bib : bif;
        const float* bh = dir ? bhb : bhf;
        float e[16];
        #pragma unroll
        for (int d = 0; d < 16; d++) e[d] = (c == 0) ? 0.f : emb[c*16 + d];
        float v[3];
        #pragma unroll
        for (int g = 0; g < 3; g++) {
            float a = bi[g*16 + jj];
            #pragma unroll
            for (int d = 0; d < 16; d++) a += e[d] * W[(g*16 + jj)*16 + d];
            v[g] = a;
        }
        v[0] = 0.5f * (v[0] + bh[jj]);
        v[1] = 0.5f * (v[1] + bh[16 + jj]);
        int o = ((dir*128 + c)*8 + (jj >> 1))*2 + (jj & 1);
        ((float*)g_tr)[o] = v[0];
        ((float*)g_tz)[o] = v[1];
        ((float*)g_tn)[o] = v[2];
    } else if (idx < 4096 + 304) {
        int t = idx - 4096;
        int cls = t >> 4, jj = t & 15;
        int c = c_map[cls];
        float v = rb[jj];
        #pragma unroll
        for (int d = 0; d < 16; d++) v += emb[c*16 + d] * rW[jj*16 + d];
        g_ctab[t] = v;
    }
}

/* ================= K1: inv_class_emb output (side stream) ================= */
__global__ void __launch_bounds__(256) k_clsemb(const int* __restrict__ ocl,
                                                const float* __restrict__ emb,
                                                float* __restrict__ out)
{
    int q = blockIdx.x * blockDim.x + threadIdx.x;
    if (q >= NSTR*4) return;
    int item = q >> 2, d4 = q & 3;
    int c = c_map[ocl[item]];
    const float4* e4 = (const float4*)emb;
    ((float4*)out)[q] = e4[c*4 + d4];
}

/* ================= K2: str_emb output + lengths (side stream) ============= */
__global__ void __launch_bounds__(256) k_stremb(const int* __restrict__ strs,
                                                const float* __restrict__ emb,
                                                float* __restrict__ out)
{
    __shared__ float4 semb[130*4];
    __shared__ unsigned char sch[8][80];
    int tid = threadIdx.x;
    const float4* e4 = (const float4*)emb;
    for (int i = tid; i < 520; i += 256) {
        float4 v = e4[i];
        if (i < 4) v = make_float4(0.f, 0.f, 0.f, 0.f);
        semb[i] = v;
    }
    int w = tid >> 5, lane = tid & 31;
    int n = blockIdx.x * 8 + w;
    const int* sp = strs + (size_t)n * 80;
    int c0 = sp[lane];
    int c1 = sp[32 + lane];
    int c2 = (lane < 16) ? sp[64 + lane] : 0;
    unsigned m0 = __ballot_sync(0xffffffffu, c0 != 0);
    unsigned m1 = __ballot_sync(0xffffffffu, c1 != 0);
    unsigned m2 = __ballot_sync(0xffffffffu, (lane < 16) && (c2 != 0));
    int len = __popc(m0) + __popc(m1) + __popc(m2);
    sch[w][lane]      = (unsigned char)c0;
    sch[w][32 + lane] = (unsigned char)c1;
    if (lane < 16) sch[w][64 + lane] = (unsigned char)c2;
    if (lane == 0) g_len[n] = (unsigned char)len;
    __syncthreads();
    float4* o4 = (float4*)out + (size_t)n * 320;
    #pragma unroll
    for (int it = 0; it < 10; it++) {
        int flat = it*32 + lane;
        int t = flat >> 2, d4 = flat & 3;
        int c = (t == len) ? EOS_TOK : (int)sch[w][t];
        o4[flat] = semb[c*4 + d4];
    }
}

/* ====== K3: bidirectional GRU — 2 sequences per 8-thread group (2x ILP) ==== */
__global__ void __launch_bounds__(128, 3) k_gru(const int* __restrict__ strs,
                                                const float* __restrict__ Whf, const float* __restrict__ bhf,
                                                const float* __restrict__ Whb, const float* __restrict__ bhb)
{
    __shared__ ull s_tr[1024], s_tz[1024], s_tn[1024];
    __shared__ unsigned char sch[32*80];
    int tid = threadIdx.x;
    int dir = blockIdx.y;
    int base = blockIdx.x * 32;     /* 32 seqs per block */

    {
        const float4* s0 = (const float4*)(g_tr + dir*1024);
        const float4* s1 = (const float4*)(g_tz + dir*1024);
        const float4* s2 = (const float4*)(g_tn + dir*1024);
        for (int i = tid; i < 512; i += 128) {
            ((float4*)s_tr)[i] = s0[i];
            ((float4*)s_tz)[i] = s1[i];
            ((float4*)s_tn)[i] = s2[i];
        }
    }
    const int* sp = strs + (size_t)base * 80;
    for (int i = tid; i < 2560; i += 128) sch[i] = (unsigned char)sp[i];
    __syncthreads();

    int j = tid & 7;
    int sg = tid >> 3;               /* group 0..15 -> seqs 2sg, 2sg+1 */
    unsigned gm = 0xFFu << (tid & 24);

    const unsigned char* chA = &sch[(2*sg)*80];
    const unsigned char* chB = &sch[(2*sg + 1)*80];

    int lenA, lenB;
    {
        int ca = 0, cb = 0;
        #pragma unroll
        for (int i = 0; i < 10; i++) {
            ca += (chA[j*10 + i] != 0);
            cb += (chB[j*10 + i] != 0);
        }
        #pragma unroll
        for (int o = 4; o; o >>= 1) {
            ca += __shfl_xor_sync(gm, ca, o, 8);
            cb += __shfl_xor_sync(gm, cb, o, 8);
        }
        lenA = ca; lenB = cb;
    }

    const float* Wp = dir ? Whb : Whf;
    const float* bh = dir ? bhb : bhf;
    int j2 = j * 2;
    ull wr[16], wz[16], wn[16];
    #pragma unroll
    for (int k = 0; k < 16; k++) {
        wr[k] = pack2(0.5f*Wp[j2*16 + k],      0.5f*Wp[(j2+1)*16 + k]);
        wz[k] = pack2(0.5f*Wp[(16+j2)*16 + k], 0.5f*Wp[(17+j2)*16 + k]);
        wn[k] = pack2(Wp[(32+j2)*16 + k],      Wp[(33+j2)*16 + k]);
    }
    ull bhn2 = pack2(bh[32 + j2], bh[33 + j2]);

    float h0a = 0.f, h1a = 0.f, h0b = 0.f, h1b = 0.f;
    int dstep = dir ? -1 : 1;
    int posA = dir ? (lenA - 1) : 0;
    int posB = dir ? (lenB - 1) : 0;
    int maxlen = lenA > lenB ? lenA : lenB;

    for (int t = 0; t < maxlen; t++, posA += dstep, posB += dstep) {
        bool vA = (t < lenA), vB = (t < lenB);
        int cA = vA ? (int)chA[posA] : 0;
        int cB = vB ? (int)chB[posB] : 0;

        ull arA = s_tr[cA*8 + j], azA = s_tz[cA*8 + j], gnA = s_tn[cA*8 + j];
        ull arB = s_tr[cB*8 + j], azB = s_tz[cB*8 + j], gnB = s_tn[cB*8 + j];
        ull arA1 = 0, azA1 = 0, anA0 = bhn2, anA1 = 0;
        ull arB1 = 0, azB1 = 0, anB0 = bhn2, anB1 = 0;
        #pragma unroll
        for (int kk = 0; kk < 8; kk++) {
            float hxa = __shfl_sync(gm, h0a, kk, 8);
            float hya = __shfl_sync(gm, h1a, kk, 8);
            float hxb = __shfl_sync(gm, h0b, kk, 8);
            float hyb = __shfl_sync(gm, h1b, kk, 8);
            ull d0a = dup2(hxa), d1a = dup2(hya);
            ull d0b = dup2(hxb), d1b = dup2(hyb);
            arA  = ffma2(wr[2*kk],   d0a, arA);
            arA1 = ffma2(wr[2*kk+1], d1a, arA1);
            azA  = ffma2(wz[2*kk],   d0a, azA);
            azA1 = ffma2(wz[2*kk+1], d1a, azA1);
            anA0 = ffma2(wn[2*kk],   d0a, anA0);
            anA1 = ffma2(wn[2*kk+1], d1a, anA1);
            arB  = ffma2(wr[2*kk],   d0b, arB);
            arB1 = ffma2(wr[2*kk+1], d1b, arB1);
            azB  = ffma2(wz[2*kk],   d0b, azB);
            azB1 = ffma2(wz[2*kk+1], d1b, azB1);
            anB0 = ffma2(wn[2*kk],   d0b, anB0);
            anB1 = ffma2(wn[2*kk+1], d1b, anB1);
        }
        /* ---- epilogue A ---- */
        {
            ull ar = fadd2(arA, arA1), az = fadd2(azA, azA1), an = fadd2(anA0, anA1);
            float srx, sry, szx, szy, ahx, ahy, gnx, gny;
            unpack2(ar, srx, sry); unpack2(az, szx, szy);
            unpack2(an, ahx, ahy); unpack2(gnA, gnx, gny);
            float r0 = sig2(srx), r1 = sig2(sry);
            float z0 = sig2(szx), z1 = sig2(szy);
            float n0 = htanh(fmaf(r0, ahx, gnx));
            float n1 = htanh(fmaf(r1, ahy, gny));
            float u0 = n0 + z0*(h0a - n0);
            float u1 = n1 + z1*(h1a - n1);
            h0a = vA ? u0 : h0a;
            h1a = vA ? u1 : h1a;
        }
        /* ---- epilogue B ---- */
        {
            ull ar = fadd2(arB, arB1), az = fadd2(azB, azB1), an = fadd2(anB0, anB1);
            float srx, sry, szx, szy, ahx, ahy, gnx, gny;
            unpack2(ar, srx, sry); unpack2(az, szx, szy);
            unpack2(an, ahx, ahy); unpack2(gnB, gnx, gny);
            float r0 = sig2(srx), r1 = sig2(sry);
            float z0 = sig2(szx), z1 = sig2(szy);
            float n0 = htanh(fmaf(r0, ahx, gnx));
            float n1 = htanh(fmaf(r1, ahy, gny));
            float u0 = n0 + z0*(h0b - n0);
            float u1 = n1 + z1*(h1b - n1);
            h0b = vB ? u0 : h0b;
            h1b = vB ? u1 : h1b;
        }
    }
    float2* hb2 = (float2*)g_hbuf;
    hb2[((size_t)dir*NSTR + base + 2*sg)*8 + j]     = make_float2(h0a, h1a);
    hb2[((size_t)dir*NSTR + base + 2*sg + 1)*8 + j] = make_float2(h0b, h1b);
}

/* ================= K4: class-branch vanilla RNN (side stream) ============= */
__global__ void __launch_bounds__(128) k_cls(const int* __restrict__ ocl,
                                             const float* __restrict__ Whh,
                                             const float* __restrict__ bhh)
{
    __shared__ float sct[19*16];
    __shared__ unsigned char soc[8*55];
    int tid = threadIdx.x;
    int base = blockIdx.x * 8;
    for (int i = tid; i < 304; i += 128) sct[i] = g_ctab[i];
    for (int i = tid; i < 440; i += 128) soc[i] = (unsigned char)ocl[base*55 + i];

    int j = tid & 15;
    float w[16];
    const float4* W4 = (const float4*)Whh;
    #pragma unroll
    for (int kk = 0; kk < 4; kk++) {
        float4 a = W4[j*4 + kk];
        w[kk*4+0]=a.x; w[kk*4+1]=a.y; w[kk*4+2]=a.z; w[kk*4+3]=a.w;
    }
    float bhv = bhh[j];
    __syncthreads();

    int s = tid >> 4;
    unsigned gmask = 0xFFFFu << (tid & 16);
    const unsigned char* oc = &soc[s * 55];
    int cnt = 0;
    #pragma unroll
    for (int i = 0; i < 4; i++) { int p = j + 16*i; cnt += (p < 55) ? (oc[p] != 18) : 0; }
    #pragma unroll
    for (int o = 8; o; o >>= 1) cnt += __shfl_xor_sync(gmask, cnt, o, 16);
    int len = cnt;

    float h = 0.f;
    for (int t = 0; t < len; t++) {
        int c = oc[t];
        float acc = sct[c*16 + j] + bhv;
        #pragma unroll
        for (int k = 0; k < 16; k++) {
            float hk = __shfl_sync(gmask, h, k, 16);
            acc += w[k]*hk;
        }
        h = htanh(acc);
    }
    g_hcls[(base + s)*16 + j] = h;
}

/* ================= K5: pooling + fusion MLP (1 item per block) ============ */
__global__ void __launch_bounds__(128) k_fuse(const float* __restrict__ W1, const float* __restrict__ b1,
                                              const float* __restrict__ W2, const float* __restrict__ b2,
                                              float* __restrict__ out)
{
    __shared__ float part[4][32];
    __shared__ float smask[56];
    __shared__ float comb[48];
    __shared__ float h1s[16];
    int t = threadIdx.x;
    int b = blockIdx.x;
    int nb = b * ITEMS;
    int grp = t >> 5, col = t & 31;

    if (t < ITEMS) smask[t] = g_len[nb + t] ? 1.f : 0.f;
    if (t == ITEMS) smask[t] = 0.f;
    __syncthreads();

    const float* hf = &g_hbuf[0];
    const float* hb = &g_hbuf[(size_t)NSTR * 16];
    float acc = 0.f;
    for (int i = grp; i < ITEMS; i += 4) {
        float hv = (col < 16) ? hf[(nb + i)*16 + col] : hb[(nb + i)*16 + (col - 16)];
        acc += smask[i] * hv;
    }
    part[grp][col] = acc;
    __syncthreads();

    if (t < 32) {
        float p = part[0][t] + part[1][t] + part[2][t] + part[3][t];
        float cnt = 0.f;
        #pragma unroll
        for (int i = 0; i < ITEMS; i++) cnt += smask[i];
        comb[16 + t] = p / (cnt + 1e-8f);
        if (t < 16) comb[t] = g_hcls[b*16 + t];
    }
    __syncthreads();
    if (t < 16) {
        float a = b1[t];
        #pragma unroll
        for (int k = 0; k < 48; k++) a += W1[t*48 + k] * comb[k];
        h1s[t] = fmaxf(a, 0.f);
    }
    __syncthreads();
    if (t < 24) {
        float o = b2[t];
        #pragma unroll
        for (int k = 0; k < 16; k++) o += W2[t*16 + k] * h1s[k];
        out[b*24 + t] = o;
    }
}

/* ---- side stream + fork/join events, created once at static init ---- */
struct SideCtx {
    cudaStream_t s;
    cudaEvent_t e_fork, e_join;
    SideCtx() {
        cudaStreamCreateWithFlags(&s, cudaStreamNonBlocking);
        cudaEventCreateWithFlags(&e_fork, cudaEventDisableTiming);
        cudaEventCreateWithFlags(&e_join, cudaEventDisableTiming);
    }
};
static SideCtx g_side;

extern "C" void kernel_launch(void* const* d_in, const int* in_sizes, int n_in,
                              void* d_out, int out_size)
{
    const int*   ocl  = (const int*)d_in[0];
    const int*   strs = (const int*)d_in[1];
    const float* emb  = (const float*)d_in[2];
    const float* rW   = (const float*)d_in[3];
    const float* rWhh = (const float*)d_in[4];
    const float* rbih = (const float*)d_in[5];
    const float* rbhh = (const float*)d_in[6];
    const float* gWf  = (const float*)d_in[7];
    const float* gWhf = (const float*)d_in[8];
    const float* gbif = (const float*)d_in[9];
    const float* gbhf = (const float*)d_in[10];
    const float* gWb  = (const float*)d_in[11];
    const float* gWhb = (const float*)d_in[12];
    const float* gbib = (const float*)d_in[13];
    const float* gbhb = (const float*)d_in[14];
    const float* W1   = (const float*)d_in[15];
    const float* b1   = (const float*)d_in[16];
    const float* W2   = (const float*)d_in[17];
    const float* b2   = (const float*)d_in[18];
    float* out = (float*)d_out;

    /* main stream: tables -> GRU -> (join) fuse */
    k_tables<<<18, 256>>>(emb, gWf, gbif, gbhf, gWb, gbib, gbhb, rW, rbih);

    /* fork: side stream runs stremb + clsemb + cls concurrently with GRU */
    cudaEventRecord(g_side.e_fork, 0);
    cudaStreamWaitEvent(g_side.s, g_side.e_fork, 0);
    k_stremb<<<7040, 256, 0, g_side.s>>>(strs, emb, out + OFF_STREMB);
    k_clsemb<<<880, 256, 0, g_side.s>>>(ocl, emb, out + OFF_CLSEMB);
    k_cls<<<128, 128, 0, g_side.s>>>(ocl, rWhh, rbhh);
    cudaEventRecord(g_side.e_join, g_side.s);

    dim3 gg(1760, 2);
    k_gru<<<gg, 128>>>(strs, gWhf, gbhf, gWhb, gbhb);

    /* join before fuse */
    cudaStreamWaitEvent(0, g_side.e_join, 0);
    k_fuse<<<1024, 128>>>(W1, b1, W2, b2, out);
}

// round 17
// speedup vs baseline: 1.1465x; 1.0249x over previous
#include <cuda_runtime.h>

typedef unsigned long long ull;

#define Bb     1024
#define ITEMS  55
#define NSTR   (Bb*ITEMS)    /* 56320 */
#define EOS_TOK 129

#define OFF_CLSEMB 24576          /* 1024*24 */
#define OFF_STREMB 925696         /* 24576 + 1024*55*16 */

/* ---- scratch (device globals) ---- */
__device__ ull   g_tr[2*128*8];       /* 0.5*(gi_r + bih_r + bhh_r), packed unit pairs */
__device__ ull   g_tz[2*128*8];       /* 0.5*(gi_z + bih_z + bhh_z) */
__device__ ull   g_tn[2*128*8];       /* gi_n + bih_n (unscaled) */
__device__ float g_ctab[19*16];
__device__ float g_hbuf[2*NSTR*16];
__device__ float g_hcls[Bb*16];
__device__ unsigned char g_len[NSTR];

__constant__ int c_map[19] = {128,93,41,91,61,34,40,37,33,63,43,47,36,42,96,48,95,46,128};

__device__ __forceinline__ float htanh(float x) {
    float r; asm("tanh.approx.f32 %0, %1;" : "=f"(r) : "f"(x)); return r;
}
__device__ __forceinline__ float sig2(float y) {   /* arg pre-halved */
    return fmaf(htanh(y), 0.5f, 0.5f);
}
__device__ __forceinline__ ull pack2(float x, float y) {
    ull r; asm("mov.b64 %0, {%1, %2};" : "=l"(r) : "f"(x), "f"(y)); return r;
}
__device__ __forceinline__ ull dup2(float x) {
    ull r; asm("mov.b64 %0, {%1, %1};" : "=l"(r) : "f"(x)); return r;
}
__device__ __forceinline__ void unpack2(ull v, float& x, float& y) {
    asm("mov.b64 {%0, %1}, %2;" : "=f"(x), "=f"(y) : "l"(v));
}
__device__ __forceinline__ ull ffma2(ull a, ull b, ull c) {
    ull d; asm("fma.rn.f32x2 %0, %1, %2, %3;" : "=l"(d) : "l"(a), "l"(b), "l"(c)); return d;
}

/* ================= K0: precompute gi tables (r,z pre-halved) ============== */
__global__ void k_tables(const float* __restrict__ emb,
                         const float* __restrict__ Wf, const float* __restrict__ bif, const float* __restrict__ bhf,
                         const float* __restrict__ Wb, const float* __restrict__ bib, const float* __restrict__ bhb,
                         const float* __restrict__ rW, const float* __restrict__ rb)
{
    int idx = blockIdx.x * blockDim.x + threadIdx.x;
    if (idx < 4096) {
        int dir = idx >> 11;
        int c   = (idx >> 4) & 127;
        int jj  = idx & 15;
        const float* W  = dir ? Wb : Wf;
        const float* bi = dir ? bib : bif;
        const float* bh = dir ? bhb : bhf;
        float e[16];
        #pragma unroll
        for (int d = 0; d < 16; d++) e[d] = (c == 0) ? 0.f : emb[c*16 + d];
        float v[3];
        #pragma unroll
        for (int g = 0; g < 3; g++) {
            float a = bi[g*16 + jj];
            #pragma unroll
            for (int d = 0; d < 16; d++) a += e[d] * W[(g*16 + jj)*16 + d];
            v[g] = a;
        }
        v[0] = 0.5f * (v[0] + bh[jj]);
        v[1] = 0.5f * (v[1] + bh[16 + jj]);
        int o = ((dir*128 + c)*8 + (jj >> 1))*2 + (jj & 1);
        ((float*)g_tr)[o] = v[0];
        ((float*)g_tz)[o] = v[1];
        ((float*)g_tn)[o] = v[2];
    } else if (idx < 4096 + 304) {
        int t = idx - 4096;
        int cls = t >> 4, jj = t & 15;
        int c = c_map[cls];
        float v = rb[jj];
        #pragma unroll
        for (int d = 0; d < 16; d++) v += emb[c*16 + d] * rW[jj*16 + d];
        g_ctab[t] = v;
    }
}

/* ================= K1: inv_class_emb output (side stream) ================= */
__global__ void __launch_bounds__(256) k_clsemb(const int* __restrict__ ocl,
                                                const float* __restrict__ emb,
                                                float* __restrict__ out)
{
    int q = blockIdx.x * blockDim.x + threadIdx.x;
    if (q >= NSTR*4) return;
    int item = q >> 2, d4 = q & 3;
    int c = c_map[ocl[item]];
    const float4* e4 = (const float4*)emb;
    ((float4*)out)[q] = e4[c*4 + d4];
}

/* ================= K2: str_emb output + lengths (side stream) ============= */
__global__ void __launch_bounds__(256) k_stremb(const int* __restrict__ strs,
                                                const float* __restrict__ emb,
                                                float* __restrict__ out)
{
    __shared__ float4 semb[130*4];
    __shared__ unsigned char sch[8][80];
    int tid = threadIdx.x;
    const float4* e4 = (const float4*)emb;
    for (int i = tid; i < 520; i += 256) {
        float4 v = e4[i];
        if (i < 4) v = make_float4(0.f, 0.f, 0.f, 0.f);
        semb[i] = v;
    }
    int w = tid >> 5, lane = tid & 31;
    int n = blockIdx.x * 8 + w;
    const int* sp = strs + (size_t)n * 80;
    int c0 = sp[lane];
    int c1 = sp[32 + lane];
    int c2 = (lane < 16) ? sp[64 + lane] : 0;
    unsigned m0 = __ballot_sync(0xffffffffu, c0 != 0);
    unsigned m1 = __ballot_sync(0xffffffffu, c1 != 0);
    unsigned m2 = __ballot_sync(0xffffffffu, (lane < 16) && (c2 != 0));
    int len = __popc(m0) + __popc(m1) + __popc(m2);
    sch[w][lane]      = (unsigned char)c0;
    sch[w][32 + lane] = (unsigned char)c1;
    if (lane < 16) sch[w][64 + lane] = (unsigned char)c2;
    if (lane == 0) g_len[n] = (unsigned char)len;
    __syncthreads();
    float4* o4 = (float4*)out + (size_t)n * 320;
    #pragma unroll
    for (int it = 0; it < 10; it++) {
        int flat = it*32 + lane;
        int t = flat >> 2, d4 = flat & 3;
        int c = (t == len) ? EOS_TOK : (int)sch[w][t];
        o4[flat] = semb[c*4 + d4];
    }
}

/* ====== K3: bidirectional GRU — 2 seqs/group, single accumulator per gate == */
__global__ void __launch_bounds__(128, 3) k_gru(const int* __restrict__ strs,
                                                const float* __restrict__ Whf, const float* __restrict__ bhf,
                                                const float* __restrict__ Whb, const float* __restrict__ bhb)
{
    __shared__ ull s_tr[1024], s_tz[1024], s_tn[1024];
    __shared__ unsigned char sch[32*80];
    int tid = threadIdx.x;
    int dir = blockIdx.y;
    int base = blockIdx.x * 32;     /* 32 seqs per block */

    {
        const float4* s0 = (const float4*)(g_tr + dir*1024);
        const float4* s1 = (const float4*)(g_tz + dir*1024);
        const float4* s2 = (const float4*)(g_tn + dir*1024);
        for (int i = tid; i < 512; i += 128) {
            ((float4*)s_tr)[i] = s0[i];
            ((float4*)s_tz)[i] = s1[i];
            ((float4*)s_tn)[i] = s2[i];
        }
    }
    const int* sp = strs + (size_t)base * 80;
    for (int i = tid; i < 2560; i += 128) sch[i] = (unsigned char)sp[i];
    __syncthreads();

    int j = tid & 7;
    int sg = tid >> 3;               /* group -> seqs 2sg, 2sg+1 */
    unsigned gm = 0xFFu << (tid & 24);

    const unsigned char* chA = &sch[(2*sg)*80];
    const unsigned char* chB = &sch[(2*sg + 1)*80];

    int lenA, lenB;
    {
        int ca = 0, cb = 0;
        #pragma unroll
        for (int i = 0; i < 10; i++) {
            ca += (chA[j*10 + i] != 0);
            cb += (chB[j*10 + i] != 0);
        }
        #pragma unroll
        for (int o = 4; o; o >>= 1) {
            ca += __shfl_xor_sync(gm, ca, o, 8);
            cb += __shfl_xor_sync(gm, cb, o, 8);
        }
        lenA = ca; lenB = cb;
    }

    const float* Wp = dir ? Whb : Whf;
    const float* bh = dir ? bhb : bhf;
    int j2 = j * 2;
    ull wr[16], wz[16], wn[16];
    #pragma unroll
    for (int k = 0; k < 16; k++) {
        wr[k] = pack2(0.5f*Wp[j2*16 + k],      0.5f*Wp[(j2+1)*16 + k]);
        wz[k] = pack2(0.5f*Wp[(16+j2)*16 + k], 0.5f*Wp[(17+j2)*16 + k]);
        wn[k] = pack2(Wp[(32+j2)*16 + k],      Wp[(33+j2)*16 + k]);
    }
    ull bhn2 = pack2(bh[32 + j2], bh[33 + j2]);

    float h0a = 0.f, h1a = 0.f, h0b = 0.f, h1b = 0.f;
    int dstep = dir ? -1 : 1;
    int posA = dir ? (lenA - 1) : 0;
    int posB = dir ? (lenB - 1) : 0;
    int maxlen = lenA > lenB ? lenA : lenB;

    for (int t = 0; t < maxlen; t++, posA += dstep, posB += dstep) {
        bool vA = (t < lenA), vB = (t < lenB);
        int cA = vA ? (int)chA[posA] : 0;
        int cB = vB ? (int)chB[posB] : 0;

        /* single accumulator per gate per seq, init from table/bias */
        ull arA = s_tr[cA*8 + j], azA = s_tz[cA*8 + j], anA = bhn2;
        ull gnA = s_tn[cA*8 + j];
        ull arB = s_tr[cB*8 + j], azB = s_tz[cB*8 + j], anB = bhn2;
        ull gnB = s_tn[cB*8 + j];
        #pragma unroll
        for (int k = 0; k < 16; k++) {
            float hka = __shfl_sync(gm, (k & 1) ? h1a : h0a, k >> 1, 8);
            float hkb = __shfl_sync(gm, (k & 1) ? h1b : h0b, k >> 1, 8);
            ull da = dup2(hka);
            ull db = dup2(hkb);
            arA = ffma2(wr[k], da, arA);
            azA = ffma2(wz[k], da, azA);
            anA = ffma2(wn[k], da, anA);
            arB = ffma2(wr[k], db, arB);
            azB = ffma2(wz[k], db, azB);
            anB = ffma2(wn[k], db, anB);
        }
        /* ---- epilogue A ---- */
        {
            float srx, sry, szx, szy, ahx, ahy, gnx, gny;
            unpack2(arA, srx, sry); unpack2(azA, szx, szy);
            unpack2(anA, ahx, ahy); unpack2(gnA, gnx, gny);
            float r0 = sig2(srx), r1 = sig2(sry);
            float z0 = sig2(szx), z1 = sig2(szy);
            float n0 = htanh(fmaf(r0, ahx, gnx));
            float n1 = htanh(fmaf(r1, ahy, gny));
            float u0 = n0 + z0*(h0a - n0);
            float u1 = n1 + z1*(h1a - n1);
            h0a = vA ? u0 : h0a;
            h1a = vA ? u1 : h1a;
        }
        /* ---- epilogue B ---- */
        {
            float srx, sry, szx, szy, ahx, ahy, gnx, gny;
            unpack2(arB, srx, sry); unpack2(azB, szx, szy);
            unpack2(anB, ahx, ahy); unpack2(gnB, gnx, gny);
            float r0 = sig2(srx), r1 = sig2(sry);
            float z0 = sig2(szx), z1 = sig2(szy);
            float n0 = htanh(fmaf(r0, ahx, gnx));
            float n1 = htanh(fmaf(r1, ahy, gny));
            float u0 = n0 + z0*(h0b - n0);
            float u1 = n1 + z1*(h1b - n1);
            h0b = vB ? u0 : h0b;
            h1b = vB ? u1 : h1b;
        }
    }
    float2* hb2 = (float2*)g_hbuf;
    hb2[((size_t)dir*NSTR + base + 2*sg)*8 + j]     = make_float2(h0a, h1a);
    hb2[((size_t)dir*NSTR + base + 2*sg + 1)*8 + j] = make_float2(h0b, h1b);
}

/* ================= K4: class-branch vanilla RNN (side stream) ============= */
__global__ void __launch_bounds__(128) k_cls(const int* __restrict__ ocl,
                                             const float* __restrict__ Whh,
                                             const float* __restrict__ bhh)
{
    __shared__ float sct[19*16];
    __shared__ unsigned char soc[8*55];
    int tid = threadIdx.x;
    int base = blockIdx.x * 8;
    for (int i = tid; i < 304; i += 128) sct[i] = g_ctab[i];
    for (int i = tid; i < 440; i += 128) soc[i] = (unsigned char)ocl[base*55 + i];

    int j = tid & 15;
    float w[16];
    const float4* W4 = (const float4*)Whh;
    #pragma unroll
    for (int kk = 0; kk < 4; kk++) {
        float4 a = W4[j*4 + kk];
        w[kk*4+0]=a.x; w[kk*4+1]=a.y; w[kk*4+2]=a.z; w[kk*4+3]=a.w;
    }
    float bhv = bhh[j];
    __syncthreads();

    int s = tid >> 4;
    unsigned gmask = 0xFFFFu << (tid & 16);
    const unsigned char* oc = &soc[s * 55];
    int cnt = 0;
    #pragma unroll
    for (int i = 0; i < 4; i++) { int p = j + 16*i; cnt += (p < 55) ? (oc[p] != 18) : 0; }
    #pragma unroll
    for (int o = 8; o; o >>= 1) cnt += __shfl_xor_sync(gmask, cnt, o, 16);
    int len = cnt;

    float h = 0.f;
    for (int t = 0; t < len; t++) {
        int c = oc[t];
        float acc = sct[c*16 + j] + bhv;
        #pragma unroll
        for (int k = 0; k < 16; k++) {
            float hk = __shfl_sync(gmask, h, k, 16);
            acc += w[k]*hk;
        }
        h = htanh(acc);
    }
    g_hcls[(base + s)*16 + j] = h;
}

/* ================= K5: pooling + fusion MLP (1 item per block) ============ */
__global__ void __launch_bounds__(128) k_fuse(const float* __restrict__ W1, const float* __restrict__ b1,
                                              const float* __restrict__ W2, const float* __restrict__ b2,
                                              float* __restrict__ out)
{
    __shared__ float part[4][32];
    __shared__ float smask[56];
    __shared__ float comb[48];
    __shared__ float h1s[16];
    int t = threadIdx.x;
    int b = blockIdx.x;
    int nb = b * ITEMS;
    int grp = t >> 5, col = t & 31;

    if (t < ITEMS) smask[t] = g_len[nb + t] ? 1.f : 0.f;
    if (t == ITEMS) smask[t] = 0.f;
    __syncthreads();

    const float* hf = &g_hbuf[0];
    const float* hb = &g_hbuf[(size_t)NSTR * 16];
    float acc = 0.f;
    for (int i = grp; i < ITEMS; i += 4) {
        float hv = (col < 16) ? hf[(nb + i)*16 + col] : hb[(nb + i)*16 + (col - 16)];
        acc += smask[i] * hv;
    }
    part[grp][col] = acc;
    __syncthreads();

    if (t < 32) {
        float p = part[0][t] + part[1][t] + part[2][t] + part[3][t];
        float cnt = 0.f;
        #pragma unroll
        for (int i = 0; i < ITEMS; i++) cnt += smask[i];
        comb[16 + t] = p / (cnt + 1e-8f);
        if (t < 16) comb[t] = g_hcls[b*16 + t];
    }
    __syncthreads();
    if (t < 16) {
        float a = b1[t];
        #pragma unroll
        for (int k = 0; k < 48; k++) a += W1[t*48 + k] * comb[k];
        h1s[t] = fmaxf(a, 0.f);
    }
    __syncthreads();
    if (t < 24) {
        float o = b2[t];
        #pragma unroll
        for (int k = 0; k < 16; k++) o += W2[t*16 + k] * h1s[k];
        out[b*24 + t] = o;
    }
}

/* ---- side stream + fork/join events, created once at static init ---- */
struct SideCtx {
    cudaStream_t s;
    cudaEvent_t e_fork, e_join;
    SideCtx() {
        cudaStreamCreateWithFlags(&s, cudaStreamNonBlocking);
        cudaEventCreateWithFlags(&e_fork, cudaEventDisableTiming);
        cudaEventCreateWithFlags(&e_join, cudaEventDisableTiming);
    }
};
static SideCtx g_side;

extern "C" void kernel_launch(void* const* d_in, const int* in_sizes, int n_in,
                              void* d_out, int out_size)
{
    const int*   ocl  = (const int*)d_in[0];
    const int*   strs = (const int*)d_in[1];
    const float* emb  = (const float*)d_in[2];
    const float* rW   = (const float*)d_in[3];
    const float* rWhh = (const float*)d_in[4];
    const float* rbih = (const float*)d_in[5];
    const float* rbhh = (const float*)d_in[6];
    const float* gWf  = (const float*)d_in[7];
    const float* gWhf = (const float*)d_in[8];
    const float* gbif = (const float*)d_in[9];
    const float* gbhf = (const float*)d_in[10];
    const float* gWb  = (const float*)d_in[11];
    const float* gWhb = (const float*)d_in[12];
    const float* gbib = (const float*)d_in[13];
    const float* gbhb = (const float*)d_in[14];
    const float* W1   = (const float*)d_in[15];
    const float* b1   = (const float*)d_in[16];
    const float* W2   = (const float*)d_in[17];
    const float* b2   = (const float*)d_in[18];
    float* out = (float*)d_out;

    /* main stream: tables -> GRU -> (join) fuse */
    k_tables<<<18, 256>>>(emb, gWf, gbif, gbhf, gWb, gbib, gbhb, rW, rbih);

    /* fork: side stream runs stremb + clsemb + cls concurrently with GRU */
    cudaEventRecord(g_side.e_fork, 0);
    cudaStreamWaitEvent(g_side.s, g_side.e_fork, 0);
    k_stremb<<<7040, 256, 0, g_side.s>>>(strs, emb, out + OFF_STREMB);
    k_clsemb<<<880, 256, 0, g_side.s>>>(ocl, emb, out + OFF_CLSEMB);
    k_cls<<<128, 128, 0, g_side.s>>>(ocl, rWhh, rbhh);
    cudaEventRecord(g_side.e_join, g_side.s);

    dim3 gg(1760, 2);
    k_gru<<<gg, 128>>>(strs, gWhf, gbhf, gWhb, gbhb);

    /* join before fuse */
    cudaStreamWaitEvent(0, g_side.e_join, 0);
    k_fuse<<<1024, 128>>>(W1, b1, W2, b2, out);
}